// round 7
// baseline (speedup 1.0000x reference)
#include <cuda_runtime.h>
#include <math.h>

// Fixed problem size (from reference): N = 200000 * 37 = 7,400,000 nodes.
#define N_NODES_TOTAL 7400000
#define NODES_PER_GRAPH 37
#define GRAPHS_PER_BLOCK 128
#define EDGE_THREADS 512

// Scratch for segment-sum result (allocation-free rule: __device__ global).
static __device__ float g_agg[N_NODES_TOTAL];

// ---------------------------------------------------------------------------
// Kernel 1: edge pass. For each edge e:
//   ew  = b2 + sum_j relu(ea[e]*W1[j] + b1[j]) * W2[j]
//   atomicAdd(agg[dst[e]], x[src[e]] * ew)
// 4 edges/thread, vectorized streaming loads with __ldcs (evict-first) so the
// 710 MB one-pass stream does not evict the L2-resident x/agg hot set.
// ---------------------------------------------------------------------------
__global__ __launch_bounds__(EDGE_THREADS)
void edge_kernel(const float* __restrict__ x,
                 const float* __restrict__ ea,
                 const float* __restrict__ W1,
                 const float* __restrict__ b1,
                 const float* __restrict__ W2,
                 const float* __restrict__ b2,
                 const int*   __restrict__ src,
                 const int*   __restrict__ dst,
                 float*       __restrict__ agg,
                 int E)
{
    // Tiny-MLP weights: uniform loads, broadcast + cached.
    const float w10 = W1[0], w11 = W1[1], w12 = W1[2], w13 = W1[3];
    const float c10 = b1[0], c11 = b1[1], c12 = b1[2], c13 = b1[3];
    const float w20 = W2[0], w21 = W2[1], w22 = W2[2], w23 = W2[3];
    const float c2  = b2[0];

    const int E4 = E >> 2;
    const int i  = blockIdx.x * blockDim.x + threadIdx.x;

    if (i < E4) {
        const int4   s = __ldcs(&((const int4*)src)[i]);
        const int4   d = __ldcs(&((const int4*)dst)[i]);
        const float4 a = __ldcs(&((const float4*)ea)[i]);

        // Issue the 4 independent gathers first so they pipeline (MLP=4)
        // under the ALU work of the tiny MLP.
        const float xs0 = __ldg(&x[s.x]);
        const float xs1 = __ldg(&x[s.y]);
        const float xs2 = __ldg(&x[s.z]);
        const float xs3 = __ldg(&x[s.w]);

        float ew0 = c2, ew1 = c2, ew2 = c2, ew3 = c2;
        ew0 = fmaf(fmaxf(fmaf(a.x, w10, c10), 0.f), w20, ew0);
        ew0 = fmaf(fmaxf(fmaf(a.x, w11, c11), 0.f), w21, ew0);
        ew0 = fmaf(fmaxf(fmaf(a.x, w12, c12), 0.f), w22, ew0);
        ew0 = fmaf(fmaxf(fmaf(a.x, w13, c13), 0.f), w23, ew0);
        ew1 = fmaf(fmaxf(fmaf(a.y, w10, c10), 0.f), w20, ew1);
        ew1 = fmaf(fmaxf(fmaf(a.y, w11, c11), 0.f), w21, ew1);
        ew1 = fmaf(fmaxf(fmaf(a.y, w12, c12), 0.f), w22, ew1);
        ew1 = fmaf(fmaxf(fmaf(a.y, w13, c13), 0.f), w23, ew1);
        ew2 = fmaf(fmaxf(fmaf(a.z, w10, c10), 0.f), w20, ew2);
        ew2 = fmaf(fmaxf(fmaf(a.z, w11, c11), 0.f), w21, ew2);
        ew2 = fmaf(fmaxf(fmaf(a.z, w12, c12), 0.f), w22, ew2);
        ew2 = fmaf(fmaxf(fmaf(a.z, w13, c13), 0.f), w23, ew2);
        ew3 = fmaf(fmaxf(fmaf(a.w, w10, c10), 0.f), w20, ew3);
        ew3 = fmaf(fmaxf(fmaf(a.w, w11, c11), 0.f), w21, ew3);
        ew3 = fmaf(fmaxf(fmaf(a.w, w12, c12), 0.f), w22, ew3);
        ew3 = fmaf(fmaxf(fmaf(a.w, w13, c13), 0.f), w23, ew3);

        atomicAdd(&agg[d.x], xs0 * ew0);
        atomicAdd(&agg[d.y], xs1 * ew1);
        atomicAdd(&agg[d.z], xs2 * ew2);
        atomicAdd(&agg[d.w], xs3 * ew3);
    }

    // Tail (E not divisible by 4) — handled by low-index threads.
    const int base = E4 << 2;
    if (i < E - base) {
        const int e = base + i;
        const float a = ea[e];
        float ew = c2;
        ew = fmaf(fmaxf(fmaf(a, w10, c10), 0.f), w20, ew);
        ew = fmaf(fmaxf(fmaf(a, w11, c11), 0.f), w21, ew);
        ew = fmaf(fmaxf(fmaf(a, w12, c12), 0.f), w22, ew);
        ew = fmaf(fmaxf(fmaf(a, w13, c13), 0.f), w23, ew);
        atomicAdd(&agg[dst[e]], __ldg(&x[src[e]]) * ew);
    }
}

// ---------------------------------------------------------------------------
// Kernel 2: per-graph head. nodes = agg + x*root + conv_bias (fused, never
// materialized), then 37->8 relu, 8->8 relu, 8->2, then the angle transform.
// One thread per graph; 128 graphs staged per block through shared memory
// with coalesced global loads. Row stride 37 in smem is bank-conflict-free
// (gcd(37,32)=1). Weight smem layout:
//   Wa[0..295] ba[296..303] Wb[304..367] bb[368..375] Wc[376..391] bc[392..393]
// ---------------------------------------------------------------------------
__global__ __launch_bounds__(GRAPHS_PER_BLOCK)
void graph_kernel(const float* __restrict__ x,
                  const float* __restrict__ agg,
                  const float* __restrict__ root_p,
                  const float* __restrict__ cbias_p,
                  const float* __restrict__ Wa, const float* __restrict__ ba,
                  const float* __restrict__ Wb, const float* __restrict__ bb,
                  const float* __restrict__ Wc, const float* __restrict__ bc,
                  float* __restrict__ out, int n_graphs)
{
    __shared__ float sW[394];
    __shared__ float tile[GRAPHS_PER_BLOCK * NODES_PER_GRAPH];

    const int tid = threadIdx.x;

    for (int i = tid; i < 394; i += GRAPHS_PER_BLOCK) {
        float v;
        if      (i < 296) v = Wa[i];
        else if (i < 304) v = ba[i - 296];
        else if (i < 368) v = Wb[i - 304];
        else if (i < 376) v = bb[i - 368];
        else if (i < 392) v = Wc[i - 376];
        else              v = bc[i - 392];
        sW[i] = v;
    }

    const float root = root_p[0];
    const float cb   = cbias_p[0];

    const int gbase = blockIdx.x * GRAPHS_PER_BLOCK;
    const int nG    = min(GRAPHS_PER_BLOCK, n_graphs - gbase);
    const int total = nG * NODES_PER_GRAPH;
    const long long off = (long long)gbase * NODES_PER_GRAPH;

    for (int i = tid; i < total; i += GRAPHS_PER_BLOCK)
        tile[i] = fmaf(x[off + i], root, agg[off + i] + cb);

    __syncthreads();

    if (tid < nG) {
        const float* row = &tile[tid * NODES_PER_GRAPH];

        float h1[8];
        #pragma unroll
        for (int j = 0; j < 8; j++) h1[j] = sW[296 + j];
        #pragma unroll 1
        for (int k = 0; k < NODES_PER_GRAPH; k++) {
            const float v = row[k];
            #pragma unroll
            for (int j = 0; j < 8; j++) h1[j] = fmaf(v, sW[k * 8 + j], h1[j]);
        }
        #pragma unroll
        for (int j = 0; j < 8; j++) h1[j] = fmaxf(h1[j], 0.f);

        float h2[8];
        #pragma unroll
        for (int j = 0; j < 8; j++) h2[j] = sW[368 + j];
        #pragma unroll
        for (int k = 0; k < 8; k++) {
            const float v = h1[k];
            #pragma unroll
            for (int j = 0; j < 8; j++) h2[j] = fmaf(v, sW[304 + k * 8 + j], h2[j]);
        }
        #pragma unroll
        for (int j = 0; j < 8; j++) h2[j] = fmaxf(h2[j], 0.f);

        float X = sW[392];
        float Y = sW[393];
        #pragma unroll
        for (int k = 0; k < 8; k++) {
            X = fmaf(h2[k], sW[376 + k * 2 + 0], X);
            Y = fmaf(h2[k], sW[376 + k * 2 + 1], Y);
        }

        const float sgn = (Y > 0.f) ? 1.f : ((Y < 0.f) ? -1.f : 0.f);
        const float ang = atanf(X / Y) + 1.5707963267948966f * sgn
                        + 3.1415926535897931f;
        out[gbase + tid] = ang * 1.9098593171027440f; // 12 / (2*pi)
    }
}

// ---------------------------------------------------------------------------
// Launch. Input order (metadata): x, edge_attr, W1, b1, W2, b2, root,
// conv_bias, Wa, ba, Wb, bb, Wc, bc, edge_index, batch_size.
// ---------------------------------------------------------------------------
extern "C" void kernel_launch(void* const* d_in, const int* in_sizes, int n_in,
                              void* d_out, int out_size)
{
    const float* x     = (const float*)d_in[0];
    const float* ea    = (const float*)d_in[1];
    const float* W1    = (const float*)d_in[2];
    const float* b1    = (const float*)d_in[3];
    const float* W2    = (const float*)d_in[4];
    const float* b2    = (const float*)d_in[5];
    const float* root  = (const float*)d_in[6];
    const float* cbias = (const float*)d_in[7];
    const float* Wa    = (const float*)d_in[8];
    const float* ba    = (const float*)d_in[9];
    const float* Wb    = (const float*)d_in[10];
    const float* bb    = (const float*)d_in[11];
    const float* Wc    = (const float*)d_in[12];
    const float* bc    = (const float*)d_in[13];
    const int*   eidx  = (const int*)d_in[14];

    const int N = in_sizes[0];              // 7,400,000 nodes
    const int E = in_sizes[14] / 2;         // 59,200,000 edges
    const int n_graphs = N / NODES_PER_GRAPH;

    const int* src = eidx;
    const int* dst = eidx + E;

    float* agg = nullptr;
    cudaGetSymbolAddress((void**)&agg, g_agg);

    // Zero the segment-sum accumulator (graph-capturable async memset).
    cudaMemsetAsync(agg, 0, (size_t)N * sizeof(float));

    {
        const int E4 = E >> 2;
        const int blocks = (E4 + EDGE_THREADS - 1) / EDGE_THREADS;
        edge_kernel<<<blocks, EDGE_THREADS>>>(x, ea, W1, b1, W2, b2,
                                              src, dst, agg, E);
    }
    {
        const int blocks = (n_graphs + GRAPHS_PER_BLOCK - 1) / GRAPHS_PER_BLOCK;
        graph_kernel<<<blocks, GRAPHS_PER_BLOCK>>>(x, agg, root, cbias,
                                                   Wa, ba, Wb, bb, Wc, bc,
                                                   (float*)d_out, n_graphs);
    }
}